// round 10
// baseline (speedup 1.0000x reference)
#include <cuda_runtime.h>
#include <cuda_bf16.h>
#include <cstdint>

// Problem constants
#define T_DIM 1024
#define N_QK  256
#define N_V   256
#define C_DIM 128
#define BD    1024
#define M_TOT (BD * C_DIM)   // 131072

// ---------------------------------------------------------------------------
// Scratch (__device__ globals; alloc-free rule)
// ---------------------------------------------------------------------------
__device__ __align__(16) __nv_bfloat16 g_qh[(size_t)M_TOT * N_QK];
__device__ __align__(16) __nv_bfloat16 g_ql[(size_t)M_TOT * N_QK];
__device__ __align__(16) __nv_bfloat16 g_kh[(size_t)M_TOT * N_QK];
__device__ __align__(16) __nv_bfloat16 g_kl[(size_t)M_TOT * N_QK];
__device__ __align__(16) __nv_bfloat16 g_vh[(size_t)M_TOT * N_V];
__device__ __align__(16) __nv_bfloat16 g_vl[(size_t)M_TOT * N_V];

__device__ __align__(16) __nv_bfloat16 g_xh[(size_t)M_TOT * T_DIM];
__device__ __align__(16) __nv_bfloat16 g_xl[(size_t)M_TOT * T_DIM];
__device__ __align__(16) __nv_bfloat16 g_wh[3 * 256 * T_DIM];
__device__ __align__(16) __nv_bfloat16 g_wl[3 * 256 * T_DIM];

// ---------------------------------------------------------------------------
// Helpers
// ---------------------------------------------------------------------------
__device__ __forceinline__ uint32_t smem_u32(const void* p) {
    uint32_t a;
    asm("{ .reg .u64 t; cvta.to.shared.u64 t, %1; cvt.u32.u64 %0, t; }"
        : "=r"(a) : "l"(p));
    return a;
}
__device__ __forceinline__ void cp16(uint32_t dst, const void* src) {
    asm volatile("cp.async.cg.shared.global [%0], [%1], 16;"
                 :: "r"(dst), "l"(src) : "memory");
}
#define CP_COMMIT() asm volatile("cp.async.commit_group;" ::: "memory")
#define CP_WAIT1()  asm volatile("cp.async.wait_group 1;" ::: "memory")

__device__ __forceinline__ void ldsm4(uint32_t* r, uint32_t addr) {
    asm volatile("ldmatrix.sync.aligned.m8n8.x4.shared.b16 {%0,%1,%2,%3}, [%4];"
                 : "=r"(r[0]), "=r"(r[1]), "=r"(r[2]), "=r"(r[3]) : "r"(addr));
}
__device__ __forceinline__ void ldsm4t(uint32_t* r, uint32_t addr) {
    asm volatile("ldmatrix.sync.aligned.m8n8.x4.trans.shared.b16 {%0,%1,%2,%3}, [%4];"
                 : "=r"(r[0]), "=r"(r[1]), "=r"(r[2]), "=r"(r[3]) : "r"(addr));
}
__device__ __forceinline__ void mma16816(float* d, const uint32_t* a,
                                         uint32_t b0, uint32_t b1) {
    asm volatile(
        "mma.sync.aligned.m16n8k16.row.col.f32.bf16.bf16.f32 "
        "{%0,%1,%2,%3}, {%4,%5,%6,%7}, {%8,%9}, {%0,%1,%2,%3};"
        : "+f"(d[0]), "+f"(d[1]), "+f"(d[2]), "+f"(d[3])
        : "r"(a[0]), "r"(a[1]), "r"(a[2]), "r"(a[3]), "r"(b0), "r"(b1));
}
__device__ __forceinline__ uint32_t pack_bf2(__nv_bfloat16 a, __nv_bfloat16 b) {
    return (uint32_t)__bfloat16_as_ushort(a) | ((uint32_t)__bfloat16_as_ushort(b) << 16);
}

// ---------------------------------------------------------------------------
// Convert kernels: fp32 -> bf16 hi/lo split
// ---------------------------------------------------------------------------
__global__ void __launch_bounds__(256) conv_x(const float* __restrict__ x)
{
    const size_t n4 = (size_t)M_TOT * T_DIM / 4;
    const size_t stride = (size_t)gridDim.x * blockDim.x;
    uint2* __restrict__ xh = (uint2*)g_xh;
    uint2* __restrict__ xl = (uint2*)g_xl;
    for (size_t i = (size_t)blockIdx.x * blockDim.x + threadIdx.x; i < n4; i += stride) {
        float4 f = ((const float4*)x)[i];
        __nv_bfloat16 h0 = __float2bfloat16(f.x);
        __nv_bfloat16 h1 = __float2bfloat16(f.y);
        __nv_bfloat16 h2 = __float2bfloat16(f.z);
        __nv_bfloat16 h3 = __float2bfloat16(f.w);
        __nv_bfloat16 l0 = __float2bfloat16(f.x - __bfloat162float(h0));
        __nv_bfloat16 l1 = __float2bfloat16(f.y - __bfloat162float(h1));
        __nv_bfloat16 l2 = __float2bfloat16(f.z - __bfloat162float(h2));
        __nv_bfloat16 l3 = __float2bfloat16(f.w - __bfloat162float(h3));
        xh[i] = make_uint2(pack_bf2(h0, h1), pack_bf2(h2, h3));
        xl[i] = make_uint2(pack_bf2(l0, l1), pack_bf2(l2, l3));
    }
}

__global__ void __launch_bounds__(256) conv_w(const float* __restrict__ Wq,
                                              const float* __restrict__ Wk,
                                              const float* __restrict__ Wv)
{
    const int mat = blockIdx.y;
    const float* W = (mat == 0) ? Wq : (mat == 1) ? Wk : Wv;
    const size_t n4 = 256 * T_DIM / 4;
    const size_t base = (size_t)mat * n4;
    uint2* __restrict__ wh = (uint2*)g_wh;
    uint2* __restrict__ wl = (uint2*)g_wl;
    for (size_t i = (size_t)blockIdx.x * blockDim.x + threadIdx.x; i < n4;
         i += (size_t)gridDim.x * blockDim.x) {
        float4 f = ((const float4*)W)[i];
        __nv_bfloat16 h0 = __float2bfloat16(f.x);
        __nv_bfloat16 h1 = __float2bfloat16(f.y);
        __nv_bfloat16 h2 = __float2bfloat16(f.z);
        __nv_bfloat16 h3 = __float2bfloat16(f.w);
        __nv_bfloat16 l0 = __float2bfloat16(f.x - __bfloat162float(h0));
        __nv_bfloat16 l1 = __float2bfloat16(f.y - __bfloat162float(h1));
        __nv_bfloat16 l2 = __float2bfloat16(f.z - __bfloat162float(h2));
        __nv_bfloat16 l3 = __float2bfloat16(f.w - __bfloat162float(h3));
        wh[base + i] = make_uint2(pack_bf2(h0, h1), pack_bf2(h2, h3));
        wl[base + i] = make_uint2(pack_bf2(l0, l1), pack_bf2(l2, l3));
    }
}

// ---------------------------------------------------------------------------
// HMMA GEMM v3: 128x128 CTA tile, 512 threads (16 warps, 4x4), 32x32 warp
// tile, BK=64, XOR-swizzled 128B rows (no padding), 2 stages, 1 CTA/SM.
// Y = Xh@Wh + Xh@Wl + Xl@Wh (fp32 acc); epilogue splits to bf16 hi/lo.
// ---------------------------------------------------------------------------
#define GT_ROWB  128                 // bytes per smem row (64 bf16, no pad)
#define GT_TILE  (128 * GT_ROWB)     // 16384
#define GOFF_AH  0
#define GOFF_AL  (1 * GT_TILE)
#define GOFF_BH  (2 * GT_TILE)
#define GOFF_BL  (3 * GT_TILE)
#define GSTAGE   (4 * GT_TILE)       // 65536
#define GEMM_SMEM (2 * GSTAGE)       // 131072
#define GNCHUNK  16                  // K=1024 / 64

// swizzled offset within a tile: row r (0..127), 16B-seg c16 (0..7)
__device__ __forceinline__ uint32_t gsw(int r, int c16) {
    return (uint32_t)(r * GT_ROWB + ((c16 ^ (r & 7)) << 4));
}

__device__ __forceinline__ void load_chunk_g(
    uint32_t st, const __nv_bfloat16* __restrict__ xh,
    const __nv_bfloat16* __restrict__ xl,
    const __nv_bfloat16* __restrict__ wh,
    const __nv_bfloat16* __restrict__ wl, int k0, int tid)
{
    // each thread: 2 segs per tile (512 thr x 2 = 1024 segs = 128 rows x 8)
#pragma unroll
    for (int t = 0; t < 2; t++) {
        int seg = tid + t * 512;
        int r   = seg >> 3;
        int c16 = seg & 7;
        uint32_t doff = gsw(r, c16);
        size_t soff = (size_t)r * T_DIM + k0 + c16 * 8;
        cp16(st + GOFF_AH + doff, xh + soff);
        cp16(st + GOFF_AL + doff, xl + soff);
        cp16(st + GOFF_BH + doff, wh + soff);
        cp16(st + GOFF_BL + doff, wl + soff);
    }
}

__global__ void __launch_bounds__(512, 1) gemm_mma(
    const float* __restrict__ bq, const float* __restrict__ bk,
    const float* __restrict__ bv)
{
    extern __shared__ __align__(16) char dyn[];

    const int tid  = threadIdx.x;
    const int lane = tid & 31;
    const int wid  = tid >> 5;          // 0..15
    const int mat  = blockIdx.x >> 1;
    const int bn   = blockIdx.x & 1;
    const int bm   = blockIdx.y;

    const int wm = (wid >> 2) * 32;     // 0,32,64,96
    const int wn = (wid & 3) * 32;      // 0,32,64,96

    const __nv_bfloat16* xh = g_xh + (size_t)bm * 128 * T_DIM;
    const __nv_bfloat16* xl = g_xl + (size_t)bm * 128 * T_DIM;
    const __nv_bfloat16* wh = g_wh + ((size_t)mat * 256 + bn * 128) * T_DIM;
    const __nv_bfloat16* wl = g_wl + ((size_t)mat * 256 + bn * 128) * T_DIM;
    const float* bias = (mat == 0) ? bq : (mat == 1) ? bk : bv;
    __nv_bfloat16* outh = ((mat == 0) ? g_qh : (mat == 1) ? g_kh : g_vh)
                          + (size_t)bm * 128 * 256 + bn * 128;
    __nv_bfloat16* outl = ((mat == 0) ? g_ql : (mat == 1) ? g_kl : g_vl)
                          + (size_t)bm * 128 * 256 + bn * 128;

    const uint32_t sbase = smem_u32(dyn);

    float acc[2][4][4];
#pragma unroll
    for (int i = 0; i < 2; i++)
#pragma unroll
        for (int j = 0; j < 4; j++)
#pragma unroll
            for (int r = 0; r < 4; r++) acc[i][j][r] = 0.0f;

    // per-lane fragment rows / segment halves
    const int ar = lane & 15;            // A row within 16-block
    const int ah16 = lane >> 4;          // A k-half (0/1 -> +8 cols = seg half)
    const int br = ((lane >> 4) << 3) + (lane & 7);  // B row within 16-block
    const int bh16 = (lane >> 3) & 1;    // B k-half

    load_chunk_g(sbase + 0 * GSTAGE, xh, xl, wh, wl, 0, tid);
    CP_COMMIT();
    load_chunk_g(sbase + 1 * GSTAGE, xh, xl, wh, wl, 64, tid);
    CP_COMMIT();

    for (int c = 0; c < GNCHUNK; c++) {
        const uint32_t st = sbase + (c & 1) * GSTAGE;
        CP_WAIT1();
        __syncthreads();

#pragma unroll
        for (int ks = 0; ks < 4; ks++) {
            // A frags: rows wm+mi*16+ar, seg c16 = ks*2 + ah16
            uint32_t ahf[2][4], alf[2][4], bhf[2][4], blf[2][4];
#pragma unroll
            for (int mi = 0; mi < 2; mi++) {
                const int row = wm + mi * 16 + ar;
                const uint32_t off = gsw(row, ks * 2 + ah16);
                ldsm4(ahf[mi], st + GOFF_AH + off);
                ldsm4(alf[mi], st + GOFF_AL + off);
            }
#pragma unroll
            for (int np = 0; np < 2; np++) {
                const int row = wn + np * 16 + br;
                const uint32_t off = gsw(row, ks * 2 + bh16);
                ldsm4(bhf[np], st + GOFF_BH + off);
                ldsm4(blf[np], st + GOFF_BL + off);
            }

#pragma unroll
            for (int mi = 0; mi < 2; mi++)
#pragma unroll
                for (int nj = 0; nj < 4; nj++) {
                    const uint32_t bh0 = bhf[nj >> 1][(nj & 1) * 2];
                    const uint32_t bh1 = bhf[nj >> 1][(nj & 1) * 2 + 1];
                    mma16816(acc[mi][nj], ahf[mi], bh0, bh1);
                    mma16816(acc[mi][nj], ahf[mi],
                             blf[nj >> 1][(nj & 1) * 2],
                             blf[nj >> 1][(nj & 1) * 2 + 1]);
                    mma16816(acc[mi][nj], alf[mi], bh0, bh1);
                }
        }

        __syncthreads();
        if (c + 2 < GNCHUNK)
            load_chunk_g(st, xh, xl, wh, wl, (c + 2) * 64, tid);
        CP_COMMIT();
    }

    // Epilogue: bias add, split to bf16 hi/lo, store both
    const int rq = lane >> 2;
    const int cq = (lane & 3) * 2;
#pragma unroll
    for (int nj = 0; nj < 4; nj++) {
        const int col = wn + nj * 8 + cq;
        const float b0 = bias[bn * 128 + col];
        const float b1 = bias[bn * 128 + col + 1];
#pragma unroll
        for (int mi = 0; mi < 2; mi++) {
            const int row = wm + mi * 16 + rq;
#pragma unroll
            for (int half = 0; half < 2; half++) {
                const float v0 = acc[mi][nj][half * 2 + 0] + b0;
                const float v1 = acc[mi][nj][half * 2 + 1] + b1;
                __nv_bfloat16 h0 = __float2bfloat16(v0);
                __nv_bfloat16 h1 = __float2bfloat16(v1);
                __nv_bfloat16 l0 = __float2bfloat16(v0 - __bfloat162float(h0));
                __nv_bfloat16 l1 = __float2bfloat16(v1 - __bfloat162float(h1));
                const size_t off = (size_t)(row + half * 8) * 256 + col;
                *(uint32_t*)(outh + off) = pack_bf2(h0, h1);
                *(uint32_t*)(outl + off) = pack_bf2(l0, l1);
            }
        }
    }
}

// ---------------------------------------------------------------------------
// Tensor-core attention (R7-exact): one CTA per (b,d)
// ---------------------------------------------------------------------------
#define P1_ROWB  80
#define P1_TILE  (128 * P1_ROWB)
#define P1_QH    0
#define P1_QL    (1 * P1_TILE)
#define P1_KH    (2 * P1_TILE)
#define P1_KL    (3 * P1_TILE)
#define P1_STAGE (4 * P1_TILE)
#define R1_SIZE  (2 * P1_STAGE)

#define S_PITCH  136
#define SH_OFF   0
#define SL_OFF   (128 * S_PITCH * 2)

#define R2_OFF   R1_SIZE
#define SF_PITCH 130
#define V_PITCHB 528
#define V_TILE   (32 * V_PITCHB)
#define V_STAGE  (2 * V_TILE)
#define ATTN_SMEM (R1_SIZE + 2 * V_STAGE)

__device__ __forceinline__ void p1_load(
    uint32_t st, const __nv_bfloat16* __restrict__ qh,
    const __nv_bfloat16* __restrict__ ql,
    const __nv_bfloat16* __restrict__ kh,
    const __nv_bfloat16* __restrict__ kl, int k0, int tid)
{
#pragma unroll
    for (int t = 0; t < 2; t++) {
        int op = tid + t * 256;
        int r  = op >> 2;
        int ch = op & 3;
        uint32_t doff = (uint32_t)(r * P1_ROWB + ch * 16);
        size_t soff = (size_t)r * N_QK + k0 + ch * 8;
        cp16(st + P1_QH + doff, qh + soff);
        cp16(st + P1_QL + doff, ql + soff);
        cp16(st + P1_KH + doff, kh + soff);
        cp16(st + P1_KL + doff, kl + soff);
    }
}

__device__ __forceinline__ void v_load(
    uint32_t st, const __nv_bfloat16* __restrict__ vh,
    const __nv_bfloat16* __restrict__ vl, int k0, int tid)
{
#pragma unroll
    for (int t = 0; t < 4; t++) {
        int op = tid + t * 256;
        int r  = op >> 5;
        int ch = op & 31;
        uint32_t doff = (uint32_t)(r * V_PITCHB + ch * 16);
        size_t soff = (size_t)(k0 + r) * N_V + ch * 8;
        cp16(st + doff, vh + soff);
        cp16(st + V_TILE + doff, vl + soff);
    }
}

__global__ void __launch_bounds__(256) attn_tc(float* __restrict__ out)
{
    extern __shared__ __align__(16) char dyn[];
    const uint32_t sb = smem_u32(dyn);

    const int tid  = threadIdx.x;
    const int lane = tid & 31;
    const int wid  = tid >> 5;
    const int bd   = blockIdx.x;

    const __nv_bfloat16* qh = g_qh + (size_t)bd * C_DIM * N_QK;
    const __nv_bfloat16* ql = g_ql + (size_t)bd * C_DIM * N_QK;
    const __nv_bfloat16* kh = g_kh + (size_t)bd * C_DIM * N_QK;
    const __nv_bfloat16* kl = g_kl + (size_t)bd * C_DIM * N_QK;
    const __nv_bfloat16* vh = g_vh + (size_t)bd * C_DIM * N_V;
    const __nv_bfloat16* vl = g_vl + (size_t)bd * C_DIM * N_V;
    float* ob = out + (size_t)bd * C_DIM * N_V;

    const int wm = (wid >> 2) * 64;
    const int wn = (wid & 3) * 32;
    const int rq = lane >> 2;
    const int cq = (lane & 3) * 2;

    // ================= Phase 1: S = q @ k^T =================
    {
        float acc[4][4][4];
#pragma unroll
        for (int i = 0; i < 4; i++)
#pragma unroll
            for (int j = 0; j < 4; j++)
#pragma unroll
                for (int r = 0; r < 4; r++) acc[i][j][r] = 0.0f;

        const uint32_t aoff = (uint32_t)((wm + (lane & 15)) * P1_ROWB + (lane >> 4) * 16);
        const uint32_t boff = (uint32_t)((wn + ((lane >> 4) << 3) + (lane & 7)) * P1_ROWB
                                         + ((lane >> 3) & 1) * 16);

        p1_load(sb + 0 * P1_STAGE, qh, ql, kh, kl, 0, tid);
        CP_COMMIT();
        p1_load(sb + 1 * P1_STAGE, qh, ql, kh, kl, 32, tid);
        CP_COMMIT();

        for (int c = 0; c < 8; c++) {
            const uint32_t st = sb + (c & 1) * P1_STAGE;
            CP_WAIT1();
            __syncthreads();

#pragma unroll
            for (int ks = 0; ks < 2; ks++) {
                const uint32_t kadd = (uint32_t)(ks * 32);
                uint32_t ah[4][4], bh[2][4];
#pragma unroll
                for (int mi = 0; mi < 4; mi++)
                    ldsm4(ah[mi], st + P1_QH + aoff + mi * (16 * P1_ROWB) + kadd);
#pragma unroll
                for (int np = 0; np < 2; np++)
                    ldsm4(bh[np], st + P1_KH + boff + np * (16 * P1_ROWB) + kadd);
#pragma unroll
                for (int mi = 0; mi < 4; mi++)
#pragma unroll
                    for (int nj = 0; nj < 4; nj++)
                        mma16816(acc[mi][nj], ah[mi], bh[nj >> 1][(nj & 1) * 2],
                                 bh[nj >> 1][(nj & 1) * 2 + 1]);

                uint32_t bl[2][4];
#pragma unroll
                for (int np = 0; np < 2; np++)
                    ldsm4(bl[np], st + P1_KL + boff + np * (16 * P1_ROWB) + kadd);
#pragma unroll
                for (int mi = 0; mi < 4; mi++)
#pragma unroll
                    for (int nj = 0; nj < 4; nj++)
                        mma16816(acc[mi][nj], ah[mi], bl[nj >> 1][(nj & 1) * 2],
                                 bl[nj >> 1][(nj & 1) * 2 + 1]);

                uint32_t al[4][4];
#pragma unroll
                for (int mi = 0; mi < 4; mi++)
                    ldsm4(al[mi], st + P1_QL + aoff + mi * (16 * P1_ROWB) + kadd);
#pragma unroll
                for (int mi = 0; mi < 4; mi++)
#pragma unroll
                    for (int nj = 0; nj < 4; nj++)
                        mma16816(acc[mi][nj], al[mi], bh[nj >> 1][(nj & 1) * 2],
                                 bh[nj >> 1][(nj & 1) * 2 + 1]);
            }

            __syncthreads();
            if (c + 2 < 8)
                p1_load(st, qh, ql, kh, kl, (c + 2) * 32, tid);
            CP_COMMIT();
        }

        float* Sf = (float*)(dyn + R2_OFF);
        const float scale = 0.0625f;
#pragma unroll
        for (int nj = 0; nj < 4; nj++) {
            const int col = wn + nj * 8 + cq;
#pragma unroll
            for (int mi = 0; mi < 4; mi++) {
                const int row = wm + mi * 16 + rq;
                Sf[row * SF_PITCH + col]           = acc[mi][nj][0] * scale;
                Sf[row * SF_PITCH + col + 1]       = acc[mi][nj][1] * scale;
                Sf[(row + 8) * SF_PITCH + col]     = acc[mi][nj][2] * scale;
                Sf[(row + 8) * SF_PITCH + col + 1] = acc[mi][nj][3] * scale;
            }
        }
    }
    __syncthreads();

    // ================= Softmax =================
    {
        float* Sf = (float*)(dyn + R2_OFF);
        if (tid < 128) {
            float* row = Sf + tid * SF_PITCH;
            float m = -1e30f;
#pragma unroll 4
            for (int j = 0; j < 128; j++) m = fmaxf(m, row[j]);
            float s = 0.0f;
#pragma unroll 4
            for (int j = 0; j < 128; j++) { float e = __expf(row[j] - m); row[j] = e; s += e; }
            float inv = 1.0f / s;
#pragma unroll 4
            for (int j = 0; j < 128; j++) row[j] *= inv;
        }
    }
    __syncthreads();

    // ================= Split S -> bf16 hi/lo =================
    {
        const float* Sf = (const float*)(dyn + R2_OFF);
        const int row = tid >> 1;
        const int c0  = (tid & 1) * 64;
#pragma unroll
        for (int j = 0; j < 64; j += 2) {
            float f0 = Sf[row * SF_PITCH + c0 + j];
            float f1 = Sf[row * SF_PITCH + c0 + j + 1];
            __nv_bfloat16 h0 = __float2bfloat16(f0);
            __nv_bfloat16 h1 = __float2bfloat16(f1);
            __nv_bfloat16 l0 = __float2bfloat16(f0 - __bfloat162float(h0));
            __nv_bfloat16 l1 = __float2bfloat16(f1 - __bfloat162float(h1));
            *(uint32_t*)(dyn + SH_OFF + (size_t)(row * S_PITCH + c0 + j) * 2) = pack_bf2(h0, h1);
            *(uint32_t*)(dyn + SL_OFF + (size_t)(row * S_PITCH + c0 + j) * 2) = pack_bf2(l0, l1);
        }
    }
    __syncthreads();

    // ================= Phase 2: Z = S @ V =================
    {
        const int wn2 = (wid & 3) * 64;
        float acc2[4][8][4];
#pragma unroll
        for (int i = 0; i < 4; i++)
#pragma unroll
            for (int j = 0; j < 8; j++)
#pragma unroll
                for (int r = 0; r < 4; r++) acc2[i][j][r] = 0.0f;

        const uint32_t aoff2 = (uint32_t)((wm + (lane & 15)) * (S_PITCH * 2)
                                          + (lane >> 4) * 16);
        const uint32_t bro = (uint32_t)((lane & 15) * V_PITCHB + (lane >> 4) * 16);

        v_load(sb + R2_OFF + 0 * V_STAGE, vh, vl, 0, tid);
        CP_COMMIT();
        v_load(sb + R2_OFF + 1 * V_STAGE, vh, vl, 32, tid);
        CP_COMMIT();

        for (int c = 0; c < 4; c++) {
            const uint32_t st = sb + R2_OFF + (c & 1) * V_STAGE;
            CP_WAIT1();
            __syncthreads();

#pragma unroll
            for (int ks = 0; ks < 2; ks++) {
                const uint32_t acol = (uint32_t)((c * 32 + ks * 16) * 2);
                const uint32_t brow = (uint32_t)(ks * 16 * V_PITCHB);

                uint32_t ah[4][4], bh[4][4];
#pragma unroll
                for (int mi = 0; mi < 4; mi++)
                    ldsm4(ah[mi], sb + SH_OFF + aoff2 + mi * (16 * S_PITCH * 2) + acol);
#pragma unroll
                for (int nb = 0; nb < 4; nb++)
                    ldsm4t(bh[nb], st + brow + bro + (uint32_t)((wn2 + nb * 16) * 2));
#pragma unroll
                for (int mi = 0; mi < 4; mi++)
#pragma unroll
                    for (int nj = 0; nj < 8; nj++)
                        mma16816(acc2[mi][nj], ah[mi], bh[nj >> 1][(nj & 1) * 2],
                                 bh[nj >> 1][(nj & 1) * 2 + 1]);

                uint32_t bl[4][4];
#pragma unroll
                for (int nb = 0; nb < 4; nb++)
                    ldsm4t(bl[nb], st + V_TILE + brow + bro + (uint32_t)((wn2 + nb * 16) * 2));
#pragma unroll
                for (int mi = 0; mi < 4; mi++)
#pragma unroll
                    for (int nj = 0; nj < 8; nj++)
                        mma16816(acc2[mi][nj], ah[mi], bl[nj >> 1][(nj & 1) * 2],
                                 bl[nj >> 1][(nj & 1) * 2 + 1]);

                uint32_t al[4][4];
#pragma unroll
                for (int mi = 0; mi < 4; mi++)
                    ldsm4(al[mi], sb + SL_OFF + aoff2 + mi * (16 * S_PITCH * 2) + acol);
#pragma unroll
                for (int mi = 0; mi < 4; mi++)
#pragma unroll
                    for (int nj = 0; nj < 8; nj++)
                        mma16816(acc2[mi][nj], al[mi], bh[nj >> 1][(nj & 1) * 2],
                                 bh[nj >> 1][(nj & 1) * 2 + 1]);
            }

            __syncthreads();
            if (c + 2 < 4)
                v_load(st, vh, vl, (c + 2) * 32, tid);
            CP_COMMIT();
        }

#pragma unroll
        for (int nj = 0; nj < 8; nj++) {
            const int col = wn2 + nj * 8 + cq;
#pragma unroll
            for (int mi = 0; mi < 4; mi++) {
                const int row = wm + mi * 16 + rq;
                *(float2*)(ob + (size_t)row * N_V + col) =
                    make_float2(acc2[mi][nj][0], acc2[mi][nj][1]);
                *(float2*)(ob + (size_t)(row + 8) * N_V + col) =
                    make_float2(acc2[mi][nj][2], acc2[mi][nj][3]);
            }
        }
    }
}

// ---------------------------------------------------------------------------
extern "C" void kernel_launch(void* const* d_in, const int* in_sizes, int n_in,
                              void* d_out, int out_size)
{
    const float* x  = (const float*)d_in[0];
    const float* Wq = (const float*)d_in[1];
    const float* bq = (const float*)d_in[2];
    const float* Wk = (const float*)d_in[3];
    const float* bk = (const float*)d_in[4];
    const float* Wv = (const float*)d_in[5];
    const float* bv = (const float*)d_in[6];
    float* out = (float*)d_out;

    conv_x<<<4096, 256>>>(x);
    conv_w<<<dim3(64, 3), 256>>>(Wq, Wk, Wv);

    cudaFuncSetAttribute(gemm_mma, cudaFuncAttributeMaxDynamicSharedMemorySize,
                         GEMM_SMEM);
    gemm_mma<<<dim3(6, 1024), 512, GEMM_SMEM>>>(bq, bk, bv);

    cudaFuncSetAttribute(attn_tc, cudaFuncAttributeMaxDynamicSharedMemorySize,
                         ATTN_SMEM);
    attn_tc<<<BD, 256, ATTN_SMEM>>>(out);
}

// round 11
// speedup vs baseline: 1.4690x; 1.4690x over previous
#include <cuda_runtime.h>
#include <cuda_bf16.h>
#include <cstdint>

// Problem constants
#define T_DIM 1024
#define N_QK  256
#define N_V   256
#define C_DIM 128
#define BD    1024
#define M_TOT (BD * C_DIM)   // 131072

// ---------------------------------------------------------------------------
// Scratch (__device__ globals; alloc-free rule)
// ---------------------------------------------------------------------------
__device__ __align__(16) __nv_bfloat16 g_qh[(size_t)M_TOT * N_QK];
__device__ __align__(16) __nv_bfloat16 g_ql[(size_t)M_TOT * N_QK];
__device__ __align__(16) __nv_bfloat16 g_kh[(size_t)M_TOT * N_QK];
__device__ __align__(16) __nv_bfloat16 g_kl[(size_t)M_TOT * N_QK];
__device__ __align__(16) __nv_bfloat16 g_vh[(size_t)M_TOT * N_V];
__device__ __align__(16) __nv_bfloat16 g_vl[(size_t)M_TOT * N_V];

__device__ __align__(16) __nv_bfloat16 g_xh[(size_t)M_TOT * T_DIM];
__device__ __align__(16) __nv_bfloat16 g_xl[(size_t)M_TOT * T_DIM];
__device__ __align__(16) __nv_bfloat16 g_wh[3 * 256 * T_DIM];
__device__ __align__(16) __nv_bfloat16 g_wl[3 * 256 * T_DIM];

// ---------------------------------------------------------------------------
// Helpers
// ---------------------------------------------------------------------------
__device__ __forceinline__ uint32_t smem_u32(const void* p) {
    uint32_t a;
    asm("{ .reg .u64 t; cvta.to.shared.u64 t, %1; cvt.u32.u64 %0, t; }"
        : "=r"(a) : "l"(p));
    return a;
}
__device__ __forceinline__ void cp16(uint32_t dst, const void* src) {
    asm volatile("cp.async.cg.shared.global [%0], [%1], 16;"
                 :: "r"(dst), "l"(src) : "memory");
}
#define CP_COMMIT() asm volatile("cp.async.commit_group;" ::: "memory")
#define CP_WAIT1()  asm volatile("cp.async.wait_group 1;" ::: "memory")

__device__ __forceinline__ void ldsm4(uint32_t* r, uint32_t addr) {
    asm volatile("ldmatrix.sync.aligned.m8n8.x4.shared.b16 {%0,%1,%2,%3}, [%4];"
                 : "=r"(r[0]), "=r"(r[1]), "=r"(r[2]), "=r"(r[3]) : "r"(addr));
}
__device__ __forceinline__ void ldsm4t(uint32_t* r, uint32_t addr) {
    asm volatile("ldmatrix.sync.aligned.m8n8.x4.trans.shared.b16 {%0,%1,%2,%3}, [%4];"
                 : "=r"(r[0]), "=r"(r[1]), "=r"(r[2]), "=r"(r[3]) : "r"(addr));
}
__device__ __forceinline__ void mma16816(float* d, const uint32_t* a,
                                         uint32_t b0, uint32_t b1) {
    asm volatile(
        "mma.sync.aligned.m16n8k16.row.col.f32.bf16.bf16.f32 "
        "{%0,%1,%2,%3}, {%4,%5,%6,%7}, {%8,%9}, {%0,%1,%2,%3};"
        : "+f"(d[0]), "+f"(d[1]), "+f"(d[2]), "+f"(d[3])
        : "r"(a[0]), "r"(a[1]), "r"(a[2]), "r"(a[3]), "r"(b0), "r"(b1));
}
__device__ __forceinline__ uint32_t pack_bf2(__nv_bfloat16 a, __nv_bfloat16 b) {
    return (uint32_t)__bfloat16_as_ushort(a) | ((uint32_t)__bfloat16_as_ushort(b) << 16);
}

// ---------------------------------------------------------------------------
// Convert kernels: fp32 -> bf16 hi/lo split
// ---------------------------------------------------------------------------
__global__ void __launch_bounds__(256) conv_x(const float* __restrict__ x)
{
    const size_t n4 = (size_t)M_TOT * T_DIM / 4;
    const size_t stride = (size_t)gridDim.x * blockDim.x;
    uint2* __restrict__ xh = (uint2*)g_xh;
    uint2* __restrict__ xl = (uint2*)g_xl;
    for (size_t i = (size_t)blockIdx.x * blockDim.x + threadIdx.x; i < n4; i += stride) {
        float4 f = ((const float4*)x)[i];
        __nv_bfloat16 h0 = __float2bfloat16(f.x);
        __nv_bfloat16 h1 = __float2bfloat16(f.y);
        __nv_bfloat16 h2 = __float2bfloat16(f.z);
        __nv_bfloat16 h3 = __float2bfloat16(f.w);
        __nv_bfloat16 l0 = __float2bfloat16(f.x - __bfloat162float(h0));
        __nv_bfloat16 l1 = __float2bfloat16(f.y - __bfloat162float(h1));
        __nv_bfloat16 l2 = __float2bfloat16(f.z - __bfloat162float(h2));
        __nv_bfloat16 l3 = __float2bfloat16(f.w - __bfloat162float(h3));
        xh[i] = make_uint2(pack_bf2(h0, h1), pack_bf2(h2, h3));
        xl[i] = make_uint2(pack_bf2(l0, l1), pack_bf2(l2, l3));
    }
}

__global__ void __launch_bounds__(256) conv_w(const float* __restrict__ Wq,
                                              const float* __restrict__ Wk,
                                              const float* __restrict__ Wv)
{
    const int mat = blockIdx.y;
    const float* W = (mat == 0) ? Wq : (mat == 1) ? Wk : Wv;
    const size_t n4 = 256 * T_DIM / 4;
    const size_t base = (size_t)mat * n4;
    uint2* __restrict__ wh = (uint2*)g_wh;
    uint2* __restrict__ wl = (uint2*)g_wl;
    for (size_t i = (size_t)blockIdx.x * blockDim.x + threadIdx.x; i < n4;
         i += (size_t)gridDim.x * blockDim.x) {
        float4 f = ((const float4*)W)[i];
        __nv_bfloat16 h0 = __float2bfloat16(f.x);
        __nv_bfloat16 h1 = __float2bfloat16(f.y);
        __nv_bfloat16 h2 = __float2bfloat16(f.z);
        __nv_bfloat16 h3 = __float2bfloat16(f.w);
        __nv_bfloat16 l0 = __float2bfloat16(f.x - __bfloat162float(h0));
        __nv_bfloat16 l1 = __float2bfloat16(f.y - __bfloat162float(h1));
        __nv_bfloat16 l2 = __float2bfloat16(f.z - __bfloat162float(h2));
        __nv_bfloat16 l3 = __float2bfloat16(f.w - __bfloat162float(h3));
        wh[base + i] = make_uint2(pack_bf2(h0, h1), pack_bf2(h2, h3));
        wl[base + i] = make_uint2(pack_bf2(l0, l1), pack_bf2(l2, l3));
    }
}

// ---------------------------------------------------------------------------
// HMMA GEMM (R7-exact): 128x128 CTA tile, 256 thr (8 warps, 2x4), 64x32
// warp tile, BK=32, 2 stages, 2 CTAs/SM.
// ---------------------------------------------------------------------------
#define ROW_B   80
#define TILE_B  (128 * ROW_B)
#define OFF_AH  0
#define OFF_AL  (1 * TILE_B)
#define OFF_BH  (2 * TILE_B)
#define OFF_BL  (3 * TILE_B)
#define STAGE_B (4 * TILE_B)
#define GEMM_SMEM (2 * STAGE_B)
#define NCHUNK  32

__device__ __forceinline__ void load_chunk(
    uint32_t st, const __nv_bfloat16* __restrict__ xh,
    const __nv_bfloat16* __restrict__ xl,
    const __nv_bfloat16* __restrict__ wh,
    const __nv_bfloat16* __restrict__ wl, int k0, int tid)
{
#pragma unroll
    for (int t = 0; t < 2; t++) {
        int op = tid + t * 256;
        int r  = op >> 2;
        int ch = op & 3;
        uint32_t doff = (uint32_t)(r * ROW_B + ch * 16);
        size_t soff = (size_t)r * T_DIM + k0 + ch * 8;
        cp16(st + OFF_AH + doff, xh + soff);
        cp16(st + OFF_AL + doff, xl + soff);
        cp16(st + OFF_BH + doff, wh + soff);
        cp16(st + OFF_BL + doff, wl + soff);
    }
}

__global__ void __launch_bounds__(256, 2) gemm_mma(
    const float* __restrict__ bq, const float* __restrict__ bk,
    const float* __restrict__ bv)
{
    extern __shared__ __align__(16) char dyn[];

    const int tid  = threadIdx.x;
    const int lane = tid & 31;
    const int wid  = tid >> 5;
    const int mat  = blockIdx.x >> 1;
    const int bn   = blockIdx.x & 1;
    const int bm   = blockIdx.y;

    const int wm = (wid >> 2) * 64;
    const int wn = (wid & 3) * 32;

    const __nv_bfloat16* xh = g_xh + (size_t)bm * 128 * T_DIM;
    const __nv_bfloat16* xl = g_xl + (size_t)bm * 128 * T_DIM;
    const __nv_bfloat16* wh = g_wh + ((size_t)mat * 256 + bn * 128) * T_DIM;
    const __nv_bfloat16* wl = g_wl + ((size_t)mat * 256 + bn * 128) * T_DIM;
    const float* bias = (mat == 0) ? bq : (mat == 1) ? bk : bv;
    __nv_bfloat16* outh = ((mat == 0) ? g_qh : (mat == 1) ? g_kh : g_vh)
                          + (size_t)bm * 128 * 256 + bn * 128;
    __nv_bfloat16* outl = ((mat == 0) ? g_ql : (mat == 1) ? g_kl : g_vl)
                          + (size_t)bm * 128 * 256 + bn * 128;

    const uint32_t sbase = smem_u32(dyn);

    float acc[4][4][4];
#pragma unroll
    for (int i = 0; i < 4; i++)
#pragma unroll
        for (int j = 0; j < 4; j++)
#pragma unroll
            for (int r = 0; r < 4; r++) acc[i][j][r] = 0.0f;

    const uint32_t aoff = (uint32_t)((wm + (lane & 15)) * ROW_B + (lane >> 4) * 16);
    const uint32_t boff = (uint32_t)((wn + ((lane >> 4) << 3) + (lane & 7)) * ROW_B
                                     + ((lane >> 3) & 1) * 16);

    load_chunk(sbase + 0 * STAGE_B, xh, xl, wh, wl, 0, tid);
    CP_COMMIT();
    load_chunk(sbase + 1 * STAGE_B, xh, xl, wh, wl, 32, tid);
    CP_COMMIT();

    for (int c = 0; c < NCHUNK; c++) {
        const uint32_t st = sbase + (c & 1) * STAGE_B;
        CP_WAIT1();
        __syncthreads();

#pragma unroll
        for (int ks = 0; ks < 2; ks++) {
            const uint32_t kadd = (uint32_t)(ks * 32);
            uint32_t ah[4][4], bh[2][4];
#pragma unroll
            for (int mi = 0; mi < 4; mi++)
                ldsm4(ah[mi], st + OFF_AH + aoff + mi * (16 * ROW_B) + kadd);
#pragma unroll
            for (int np = 0; np < 2; np++)
                ldsm4(bh[np], st + OFF_BH + boff + np * (16 * ROW_B) + kadd);
#pragma unroll
            for (int mi = 0; mi < 4; mi++)
#pragma unroll
                for (int nj = 0; nj < 4; nj++)
                    mma16816(acc[mi][nj], ah[mi], bh[nj >> 1][(nj & 1) * 2],
                             bh[nj >> 1][(nj & 1) * 2 + 1]);

            uint32_t bl[2][4];
#pragma unroll
            for (int np = 0; np < 2; np++)
                ldsm4(bl[np], st + OFF_BL + boff + np * (16 * ROW_B) + kadd);
#pragma unroll
            for (int mi = 0; mi < 4; mi++)
#pragma unroll
                for (int nj = 0; nj < 4; nj++)
                    mma16816(acc[mi][nj], ah[mi], bl[nj >> 1][(nj & 1) * 2],
                             bl[nj >> 1][(nj & 1) * 2 + 1]);

            uint32_t al[4][4];
#pragma unroll
            for (int mi = 0; mi < 4; mi++)
                ldsm4(al[mi], st + OFF_AL + aoff + mi * (16 * ROW_B) + kadd);
#pragma unroll
            for (int mi = 0; mi < 4; mi++)
#pragma unroll
                for (int nj = 0; nj < 4; nj++)
                    mma16816(acc[mi][nj], al[mi], bh[nj >> 1][(nj & 1) * 2],
                             bh[nj >> 1][(nj & 1) * 2 + 1]);
        }

        __syncthreads();
        if (c + 2 < NCHUNK)
            load_chunk(st, xh, xl, wh, wl, (c + 2) * 32, tid);
        CP_COMMIT();
    }

    const int rq = lane >> 2;
    const int cq = (lane & 3) * 2;
#pragma unroll
    for (int nj = 0; nj < 4; nj++) {
        const int col = wn + nj * 8 + cq;
        const float b0 = bias[bn * 128 + col];
        const float b1 = bias[bn * 128 + col + 1];
#pragma unroll
        for (int mi = 0; mi < 4; mi++) {
            const int row = wm + mi * 16 + rq;
#pragma unroll
            for (int half = 0; half < 2; half++) {
                const float v0 = acc[mi][nj][half * 2 + 0] + b0;
                const float v1 = acc[mi][nj][half * 2 + 1] + b1;
                __nv_bfloat16 h0 = __float2bfloat16(v0);
                __nv_bfloat16 h1 = __float2bfloat16(v1);
                __nv_bfloat16 l0 = __float2bfloat16(v0 - __bfloat162float(h0));
                __nv_bfloat16 l1 = __float2bfloat16(v1 - __bfloat162float(h1));
                const size_t off = (size_t)(row + half * 8) * 256 + col;
                *(uint32_t*)(outh + off) = pack_bf2(h0, h1);
                *(uint32_t*)(outl + off) = pack_bf2(l0, l1);
            }
        }
    }
}

// ---------------------------------------------------------------------------
// Tensor-core attention v2: 2 CTAs/SM target.
//  - register-resident softmax (quad shfl + cross-warp partial bufs)
//  - phase 2 split into two 128-col halves (acc2 = 64 regs)
// smem: R1 81920 (P1 stages; reused for S hi/lo) + bufs 4096 + V 17408
//     = 103424
// ---------------------------------------------------------------------------
#define P1_ROWB  80
#define P1_TILE  (128 * P1_ROWB)
#define P1_QH    0
#define P1_QL    (1 * P1_TILE)
#define P1_KH    (2 * P1_TILE)
#define P1_KL    (3 * P1_TILE)
#define P1_STAGE (4 * P1_TILE)          // 40960
#define R1_SIZE  (2 * P1_STAGE)         // 81920

#define S_PITCH  136                    // bf16 elems (272B rows)
#define SH_OFF   0
#define SL_OFF   (128 * S_PITCH * 2)    // 34816

#define RB_OFF   R1_SIZE                // region B
#define BUFMAX_OFF RB_OFF               // 128*4 fp32 = 2048
#define BUFSUM_OFF (RB_OFF + 2048)      // 2048
#define V_OFF    (RB_OFF + 4096)
#define V2_PITCHB 272                   // 128 bf16 cols + 16B pad
#define V2_TILE  (16 * V2_PITCHB)       // 4352
#define V2_STAGE (2 * V2_TILE)          // hi + lo = 8704
#define ATTN_SMEM (V_OFF + 2 * V2_STAGE)   // 103424

__device__ __forceinline__ void p1_load(
    uint32_t st, const __nv_bfloat16* __restrict__ qh,
    const __nv_bfloat16* __restrict__ ql,
    const __nv_bfloat16* __restrict__ kh,
    const __nv_bfloat16* __restrict__ kl, int k0, int tid)
{
#pragma unroll
    for (int t = 0; t < 2; t++) {
        int op = tid + t * 256;
        int r  = op >> 2;
        int ch = op & 3;
        uint32_t doff = (uint32_t)(r * P1_ROWB + ch * 16);
        size_t soff = (size_t)r * N_QK + k0 + ch * 8;
        cp16(st + P1_QH + doff, qh + soff);
        cp16(st + P1_QL + doff, ql + soff);
        cp16(st + P1_KH + doff, kh + soff);
        cp16(st + P1_KL + doff, kl + soff);
    }
}

// 16 rows x 128 cols (half h), hi + lo
__device__ __forceinline__ void v_load2(
    uint32_t st, const __nv_bfloat16* __restrict__ vh,
    const __nv_bfloat16* __restrict__ vl, int k0, int h, int tid)
{
    int r  = tid >> 4;            // 0..15
    int ch = tid & 15;            // 0..15 (16B chunks of 256B row)
    uint32_t doff = (uint32_t)(r * V2_PITCHB + ch * 16);
    size_t soff = (size_t)(k0 + r) * N_V + h * 128 + ch * 8;
    cp16(st + doff, vh + soff);
    cp16(st + V2_TILE + doff, vl + soff);
}

__global__ void __launch_bounds__(256, 2) attn_tc(float* __restrict__ out)
{
    extern __shared__ __align__(16) char dyn[];
    const uint32_t sb = smem_u32(dyn);

    const int tid  = threadIdx.x;
    const int lane = tid & 31;
    const int wid  = tid >> 5;
    const int bd   = blockIdx.x;

    const __nv_bfloat16* qh = g_qh + (size_t)bd * C_DIM * N_QK;
    const __nv_bfloat16* ql = g_ql + (size_t)bd * C_DIM * N_QK;
    const __nv_bfloat16* kh = g_kh + (size_t)bd * C_DIM * N_QK;
    const __nv_bfloat16* kl = g_kl + (size_t)bd * C_DIM * N_QK;
    const __nv_bfloat16* vh = g_vh + (size_t)bd * C_DIM * N_V;
    const __nv_bfloat16* vl = g_vl + (size_t)bd * C_DIM * N_V;
    float* ob = out + (size_t)bd * C_DIM * N_V;

    const int wm = (wid >> 2) * 64;      // 0 or 64
    const int wn = (wid & 3) * 32;       // phase-1 col slice
    const int rq = lane >> 2;
    const int cq = (lane & 3) * 2;

    float* bufMax = (float*)(dyn + BUFMAX_OFF);
    float* bufSum = (float*)(dyn + BUFSUM_OFF);

    // ================= Phase 1: S = q @ k^T (regs) =================
    float acc[4][4][4];
#pragma unroll
    for (int i = 0; i < 4; i++)
#pragma unroll
        for (int j = 0; j < 4; j++)
#pragma unroll
            for (int r = 0; r < 4; r++) acc[i][j][r] = 0.0f;

    {
        const uint32_t aoff = (uint32_t)((wm + (lane & 15)) * P1_ROWB + (lane >> 4) * 16);
        const uint32_t boff = (uint32_t)((wn + ((lane >> 4) << 3) + (lane & 7)) * P1_ROWB
                                         + ((lane >> 3) & 1) * 16);

        p1_load(sb + 0 * P1_STAGE, qh, ql, kh, kl, 0, tid);
        CP_COMMIT();
        p1_load(sb + 1 * P1_STAGE, qh, ql, kh, kl, 32, tid);
        CP_COMMIT();

        for (int c = 0; c < 8; c++) {
            const uint32_t st = sb + (c & 1) * P1_STAGE;
            CP_WAIT1();
            __syncthreads();

#pragma unroll
            for (int ks = 0; ks < 2; ks++) {
                const uint32_t kadd = (uint32_t)(ks * 32);
                uint32_t ah[4][4], bh[2][4];
#pragma unroll
                for (int mi = 0; mi < 4; mi++)
                    ldsm4(ah[mi], st + P1_QH + aoff + mi * (16 * P1_ROWB) + kadd);
#pragma unroll
                for (int np = 0; np < 2; np++)
                    ldsm4(bh[np], st + P1_KH + boff + np * (16 * P1_ROWB) + kadd);
#pragma unroll
                for (int mi = 0; mi < 4; mi++)
#pragma unroll
                    for (int nj = 0; nj < 4; nj++)
                        mma16816(acc[mi][nj], ah[mi], bh[nj >> 1][(nj & 1) * 2],
                                 bh[nj >> 1][(nj & 1) * 2 + 1]);

                uint32_t bl[2][4];
#pragma unroll
                for (int np = 0; np < 2; np++)
                    ldsm4(bl[np], st + P1_KL + boff + np * (16 * P1_ROWB) + kadd);
#pragma unroll
                for (int mi = 0; mi < 4; mi++)
#pragma unroll
                    for (int nj = 0; nj < 4; nj++)
                        mma16816(acc[mi][nj], ah[mi], bl[nj >> 1][(nj & 1) * 2],
                                 bl[nj >> 1][(nj & 1) * 2 + 1]);

                uint32_t al[4][4];
#pragma unroll
                for (int mi = 0; mi < 4; mi++)
                    ldsm4(al[mi], st + P1_QL + aoff + mi * (16 * P1_ROWB) + kadd);
#pragma unroll
                for (int mi = 0; mi < 4; mi++)
#pragma unroll
                    for (int nj = 0; nj < 4; nj++)
                        mma16816(acc[mi][nj], al[mi], bh[nj >> 1][(nj & 1) * 2],
                                 bh[nj >> 1][(nj & 1) * 2 + 1]);
            }

            __syncthreads();
            if (c + 2 < 8)
                p1_load(st, qh, ql, kh, kl, (c + 2) * 32, tid);
            CP_COMMIT();
        }
    }
    // last stage consumed; region A is free after this point for S hi/lo

    // ================= Softmax from registers =================
    {
        const float scale = 0.0625f;     // 1/sqrt(256)
#pragma unroll
        for (int mi = 0; mi < 4; mi++)
#pragma unroll
            for (int nj = 0; nj < 4; nj++)
#pragma unroll
                for (int r = 0; r < 4; r++) acc[mi][nj][r] *= scale;

        // local max per (mi, half)
        float m[4][2];
#pragma unroll
        for (int mi = 0; mi < 4; mi++)
#pragma unroll
            for (int h = 0; h < 2; h++) {
                float v = -1e30f;
#pragma unroll
                for (int nj = 0; nj < 4; nj++) {
                    v = fmaxf(v, acc[mi][nj][h * 2]);
                    v = fmaxf(v, acc[mi][nj][h * 2 + 1]);
                }
                v = fmaxf(v, __shfl_xor_sync(0xffffffffu, v, 1));
                v = fmaxf(v, __shfl_xor_sync(0xffffffffu, v, 2));
                m[mi][h] = v;
            }
        if ((lane & 3) == 0) {
#pragma unroll
            for (int mi = 0; mi < 4; mi++)
#pragma unroll
                for (int h = 0; h < 2; h++) {
                    int row = wm + mi * 16 + rq + h * 8;
                    bufMax[row * 4 + (wid & 3)] = m[mi][h];
                }
        }
        __syncthreads();

        float Mx[4][2];
#pragma unroll
        for (int mi = 0; mi < 4; mi++)
#pragma unroll
            for (int h = 0; h < 2; h++) {
                int row = wm + mi * 16 + rq + h * 8;
                float a0 = bufMax[row * 4 + 0], a1 = bufMax[row * 4 + 1];
                float a2 = bufMax[row * 4 + 2], a3 = bufMax[row * 4 + 3];
                Mx[mi][h] = fmaxf(fmaxf(a0, a1), fmaxf(a2, a3));
            }

        // exp + local sums
        float s[4][2];
#pragma unroll
        for (int mi = 0; mi < 4; mi++)
#pragma unroll
            for (int h = 0; h < 2; h++) {
                float v = 0.0f;
#pragma unroll
                for (int nj = 0; nj < 4; nj++) {
                    float e0 = __expf(acc[mi][nj][h * 2]     - Mx[mi][h]);
                    float e1 = __expf(acc[mi][nj][h * 2 + 1] - Mx[mi][h]);
                    acc[mi][nj][h * 2]     = e0;
                    acc[mi][nj][h * 2 + 1] = e1;
                    v += e0 + e1;
                }
                v += __shfl_xor_sync(0xffffffffu, v, 1);
                v += __shfl_xor_sync(0xffffffffu, v, 2);
                s[mi][h] = v;
            }
        if ((lane & 3) == 0) {
#pragma unroll
            for (int mi = 0; mi < 4; mi++)
#pragma unroll
                for (int h = 0; h < 2; h++) {
                    int row = wm + mi * 16 + rq + h * 8;
                    bufSum[row * 4 + (wid & 3)] = s[mi][h];
                }
        }
        __syncthreads();

        // normalize, split, store S hi/lo to region A
#pragma unroll
        for (int mi = 0; mi < 4; mi++)
#pragma unroll
            for (int h = 0; h < 2; h++) {
                int row = wm + mi * 16 + rq + h * 8;
                float inv = 1.0f / (bufSum[row * 4 + 0] + bufSum[row * 4 + 1]
                                  + bufSum[row * 4 + 2] + bufSum[row * 4 + 3]);
#pragma unroll
                for (int nj = 0; nj < 4; nj++) {
                    int col = wn + nj * 8 + cq;
                    float f0 = acc[mi][nj][h * 2]     * inv;
                    float f1 = acc[mi][nj][h * 2 + 1] * inv;
                    __nv_bfloat16 h0 = __float2bfloat16(f0);
                    __nv_bfloat16 h1 = __float2bfloat16(f1);
                    __nv_bfloat16 l0 = __float2bfloat16(f0 - __bfloat162float(h0));
                    __nv_bfloat16 l1 = __float2bfloat16(f1 - __bfloat162float(h1));
                    uint32_t off = (uint32_t)(row * S_PITCH + col) * 2;
                    *(uint32_t*)(dyn + SH_OFF + off) = pack_bf2(h0, h1);
                    *(uint32_t*)(dyn + SL_OFF + off) = pack_bf2(l0, l1);
                }
            }
    }
    __syncthreads();

    // ================= Phase 2: Z = S @ V, two 128-col halves =================
    const uint32_t aoff2 = (uint32_t)((wm + (lane & 15)) * (S_PITCH * 2)
                                      + (lane >> 4) * 16);
    const uint32_t bro = (uint32_t)((lane & 15) * V2_PITCHB + (lane >> 4) * 16);
    const int wn2 = (wid & 3) * 32;     // col slice within the 128-col half

#pragma unroll
    for (int h = 0; h < 2; h++) {
        float acc2[4][4][4];
#pragma unroll
        for (int i = 0; i < 4; i++)
#pragma unroll
            for (int j = 0; j < 4; j++)
#pragma unroll
                for (int r = 0; r < 4; r++) acc2[i][j][r] = 0.0f;

        v_load2(sb + V_OFF + 0 * V2_STAGE, vh, vl, 0, h, tid);
        CP_COMMIT();
        v_load2(sb + V_OFF + 1 * V2_STAGE, vh, vl, 16, h, tid);
        CP_COMMIT();

        for (int c = 0; c < 8; c++) {
            const uint32_t st = sb + V_OFF + (c & 1) * V2_STAGE;
            CP_WAIT1();
            __syncthreads();

            const uint32_t acol = (uint32_t)(c * 32);   // 16 elems * 2B

            uint32_t ah[4][4], bh[2][4];
#pragma unroll
            for (int mi = 0; mi < 4; mi++)
                ldsm4(ah[mi], sb + SH_OFF + aoff2 + mi * (16 * S_PITCH * 2) + acol);
#pragma unroll
            for (int nb = 0; nb < 2; nb++)
                ldsm4t(bh[nb], st + bro + (uint32_t)((wn2 + nb * 16) * 2));
#pragma unroll
            for (int mi = 0; mi < 4; mi++)
#pragma unroll
                for (int nj = 0; nj < 4; nj++)
                    mma16816(acc2[mi][nj], ah[mi], bh[nj >> 1][(nj & 1) * 2],
                             bh[nj >> 1][(nj & 1) * 2 + 1]);

            uint32_t bl[2][4];
#pragma unroll
            for (int nb = 0; nb < 2; nb++)
                ldsm4t(bl[nb], st + V2_TILE + bro + (uint32_t)((wn2 + nb * 16) * 2));
#pragma unroll
            for (int mi = 0; mi < 4; mi++)
#pragma unroll
                for (int nj = 0; nj < 4; nj++)
                    mma16816(acc2[mi][nj], ah[mi], bl[nj >> 1][(nj & 1) * 2],
                             bl[nj >> 1][(nj & 1) * 2 + 1]);

            uint32_t al[4][4];
#pragma unroll
            for (int mi = 0; mi < 4; mi++)
                ldsm4(al[mi], sb + SL_OFF + aoff2 + mi * (16 * S_PITCH * 2) + acol);
#pragma unroll
            for (int mi = 0; mi < 4; mi++)
#pragma unroll
                for (int nj = 0; nj < 4; nj++)
                    mma16816(acc2[mi][nj], al[mi], bh[nj >> 1][(nj & 1) * 2],
                             bh[nj >> 1][(nj & 1) * 2 + 1]);

            __syncthreads();
            if (c + 2 < 8)
                v_load2(st, vh, vl, (c + 2) * 16, h, tid);
            CP_COMMIT();
        }

#pragma unroll
        for (int nj = 0; nj < 4; nj++) {
            const int col = h * 128 + wn2 + nj * 8 + cq;
#pragma unroll
            for (int mi = 0; mi < 4; mi++) {
                const int row = wm + mi * 16 + rq;
                *(float2*)(ob + (size_t)row * N_V + col) =
                    make_float2(acc2[mi][nj][0], acc2[mi][nj][1]);
                *(float2*)(ob + (size_t)(row + 8) * N_V + col) =
                    make_float2(acc2[mi][nj][2], acc2[mi][nj][3]);
            }
        }
        __syncthreads();   // stage region reuse across h
    }
}

// ---------------------------------------------------------------------------
extern "C" void kernel_launch(void* const* d_in, const int* in_sizes, int n_in,
                              void* d_out, int out_size)
{
    const float* x  = (const float*)d_in[0];
    const float* Wq = (const float*)d_in[1];
    const float* bq = (const float*)d_in[2];
    const float* Wk = (const float*)d_in[3];
    const float* bk = (const float*)d_in[4];
    const float* Wv = (const float*)d_in[5];
    const float* bv = (const float*)d_in[6];
    float* out = (float*)d_out;

    conv_x<<<4096, 256>>>(x);
    conv_w<<<dim3(64, 3), 256>>>(Wq, Wk, Wv);

    cudaFuncSetAttribute(gemm_mma, cudaFuncAttributeMaxDynamicSharedMemorySize,
                         GEMM_SMEM);
    gemm_mma<<<dim3(6, 1024), 256, GEMM_SMEM>>>(bq, bk, bv);

    cudaFuncSetAttribute(attn_tc, cudaFuncAttributeMaxDynamicSharedMemorySize,
                         ATTN_SMEM);
    attn_tc<<<BD, 256, ATTN_SMEM>>>(out);
}